// round 12
// baseline (speedup 1.0000x reference)
#include <cuda_runtime.h>
#include <cstdint>

#define BATCH 4096

// ---- 16KB chunks (4096 floats) over concatenated logits ----
#define CHUNK_FLOATS 4096
#define CHUNK_BYTES  16384
#define C3_END 8192              // L3: half-row per chunk (2 chunks/row)
#define C2_END 10240             // L2: 2 rows/chunk
#define C1_END 10752             // L1: 8 rows/chunk
#define NCHUNK 10880             // L0: 32 rows/chunk

#define NB_CE 592                // 4 CTAs/SM x 148
#define NBD 8                    // dep folded into CTAs 0..7
#define NSTAGE 3

__device__ float g_part[NB_CE];
__device__ float g_dep[NBD];
__device__ int   g_done;         // zero-init; self-resets each replay

__device__ __forceinline__ float vec_expsum(float4 v) {
    return __expf(v.x) + __expf(v.y) + __expf(v.z) + __expf(v.w);
}
__device__ __forceinline__ float warp_sum(float s) {
    #pragma unroll
    for (int off = 16; off; off >>= 1)
        s += __shfl_xor_sync(0xffffffffu, s, off);
    return s;
}
__device__ __forceinline__ uint32_t smem_u32(const void* p) {
    return (uint32_t)__cvta_generic_to_shared(p);
}
__device__ __forceinline__ void mbar_init(uint32_t a) {
    asm volatile("mbarrier.init.shared.b64 [%0], 1;" :: "r"(a) : "memory");
}
__device__ __forceinline__ void mbar_wait(uint32_t a, int parity) {
    asm volatile(
        "{\n\t.reg .pred P;\n\t"
        "W%=:\n\t"
        "mbarrier.try_wait.parity.acquire.cta.shared::cta.b64 P, [%0], %1, 0x989680;\n\t"
        "@P bra D%=;\n\t"
        "bra W%=;\n\t"
        "D%=:\n\t}"
        :: "r"(a), "r"(parity) : "memory");
}
__device__ __forceinline__ void bulk_load(uint32_t dst, const void* src,
                                          uint32_t bytes, uint32_t mbar) {
    asm volatile("mbarrier.arrive.expect_tx.shared.b64 _, [%0], %1;"
                 :: "r"(mbar), "r"(bytes) : "memory");
    asm volatile(
        "cp.async.bulk.shared::cluster.global.mbarrier::complete_tx::bytes "
        "[%0], [%1], %2, [%3];"
        :: "r"(dst), "l"(src), "r"(bytes), "r"(mbar) : "memory");
}

__global__ void __launch_bounds__(128)
fused_kernel(const float* __restrict__ o0, const float* __restrict__ o1,
             const float* __restrict__ o2, const float* __restrict__ o3,
             const int* __restrict__ targets,
             const int* __restrict__ p0, const int* __restrict__ p1,
             const int* __restrict__ p2, const int* __restrict__ p3,
             const int* __restrict__ v01, const int* __restrict__ v12,
             const int* __restrict__ v23,
             float* __restrict__ out) {
    extern __shared__ float stage[];              // NSTAGE * 4096 floats
    __shared__ unsigned long long mbar_s[NSTAGE];
    __shared__ float sws[2][4];
    __shared__ float swr[4];
    __shared__ bool  is_last;

    const int bid = blockIdx.x;
    const int tid = threadIdx.x;
    const int wid = tid >> 5;
    const int lid = tid & 31;

    float acc = 0.0f;
    float carry = 0.0f, tcarry = 0.0f;   // t0-private L3 half-row state

    // per-CTA chunk counts
    const int n3 = (4096 - bid + 591) / 592;   // L3 row tasks (2 chunks each)
    const int n2 = (2048 - bid + 591) / 592;   // L2 chunks
    const int n1 = (bid < 512) ? ((512 - bid + 591) / 592) : 0;
    const int n0 = (bid < 128) ? ((128 - bid + 591) / 592) : 0;
    const int ktot = 2 * n3 + n2 + n1 + n0;

    auto seq = [&](int k) -> int {
        if (k < 2 * n3) { int t = k >> 1; return 2 * (bid + t * 592) + (k & 1); }
        k -= 2 * n3;
        if (k < n2) return 8192 + bid + k * 592;
        k -= n2;
        if (k < n1) return 10240 + bid + k * 592;
        k -= n1;
        return 10752 + bid + k * 592;
    };
    auto src_of = [&](int c) -> const float* {
        if (c < C3_END) return o3 + (size_t)c * CHUNK_FLOATS;
        if (c < C2_END) return o2 + (size_t)(c - C3_END) * CHUNK_FLOATS;
        if (c < C1_END) return o1 + (size_t)(c - C2_END) * CHUNK_FLOATS;
        return o0 + (size_t)(c - C1_END) * CHUNK_FLOATS;
    };

    uint32_t mb[NSTAGE], stg[NSTAGE];
    #pragma unroll
    for (int s = 0; s < NSTAGE; s++) {
        mb[s]  = smem_u32(&mbar_s[s]);
        stg[s] = smem_u32(&stage[s * CHUNK_FLOATS]);
    }
    if (tid == 0) {
        #pragma unroll
        for (int s = 0; s < NSTAGE; s++) mbar_init(mb[s]);
    }
    __syncthreads();

    if (tid == 0) {
        #pragma unroll
        for (int kp = 0; kp < NSTAGE; kp++)
            bulk_load(stg[kp], src_of(seq(kp)), CHUNK_BYTES, mb[kp]);
    }

    // ---- dep work folded into CTAs 0..7, hidden under pipeline fill ----
    if (bid < NBD) {
        float cnt = 0.0f;
        #pragma unroll
        for (int rep = 0; rep < 4; rep++) {
            const int i = bid * 512 + rep * 128 + tid;
            const int a = p0[i], b = p1[i], cc = p2[i], e = p3[i];
            cnt += (v01[a * 512   + b ] == 0) ? 1.0f : 0.0f;
            cnt += (v12[b * 2048  + cc] == 0) ? 1.0f : 0.0f;
            cnt += (v23[cc * 8192 + e ] == 0) ? 1.0f : 0.0f;
        }
        cnt = warp_sum(cnt);
        if (lid == 0) swr[wid] = cnt;
        __syncthreads();
        if (tid == 0) g_dep[bid] = (swr[0] + swr[1]) + (swr[2] + swr[3]);
        __syncthreads();
    }

    // ---- main pipelined loop ----
    for (int k = 0; k < ktot; k++) {
        const int s = k % NSTAGE;
        const int parity = (k / NSTAGE) & 1;
        const int pb = k & 1;
        const int c = seq(k);
        mbar_wait(mb[s], parity);

        const float*  sf = stage + s * CHUNK_FLOATS;
        const float4* st = (const float4*)sf;

        if (c < C2_END) {
            // L3 half-row or L2 2-rows: each warp covers 256 float4 (8/lane).
            int ti0 = 0, ti1 = 0;
            if (tid == 0) {
                if (c < C3_END) {
                    ti0 = targets[(c >> 1) * 4 + 3];
                } else {
                    const int rb = (c - C3_END) * 2;
                    ti0 = targets[(rb + 0) * 4 + 2];
                    ti1 = targets[(rb + 1) * 4 + 2];
                }
            }
            const float4* wp = st + wid * 256;
            float4 v[8];
            #pragma unroll
            for (int j = 0; j < 8; j++) v[j] = wp[j * 32 + lid];
            float a0 = vec_expsum(v[0]) + vec_expsum(v[4]);
            float a1 = vec_expsum(v[1]) + vec_expsum(v[5]);
            float a2 = vec_expsum(v[2]) + vec_expsum(v[6]);
            float a3 = vec_expsum(v[3]) + vec_expsum(v[7]);
            float sw = warp_sum((a0 + a1) + (a2 + a3));
            if (lid == 0) sws[pb][wid] = sw;
            __syncthreads();

            if (tid == 0) {
                float csum = (sws[pb][0] + sws[pb][1]) + (sws[pb][2] + sws[pb][3]);
                if (c < C3_END) {
                    const int half = c & 1;
                    if (half == 0) {
                        carry = csum;
                        if (ti0 < 4096) tcarry = sf[ti0];
                    } else {
                        float tval = (ti0 >= 4096) ? sf[ti0 - 4096] : tcarry;
                        acc += __logf(carry + csum) - tval;
                    }
                } else {
                    float s0 = sws[pb][0] + sws[pb][1];
                    float s1 = sws[pb][2] + sws[pb][3];
                    acc += (__logf(s0) - sf[ti0]) + (__logf(s1) - sf[2048 + ti1]);
                }
            }
        } else if (c < C1_END) {
            // L1: 8 rows of 512; warp w owns rows 2w, 2w+1 (4 float4/lane each).
            const int rb = (c - C2_END) * 8;
            int tA = 0, tB = 0;
            if (lid == 0) {
                tA = targets[(rb + 2 * wid + 0) * 4 + 1];
                tB = targets[(rb + 2 * wid + 1) * 4 + 1];
            }
            const float4* pA = st + (2 * wid + 0) * 128;
            const float4* pB = st + (2 * wid + 1) * 128;
            float4 vA[4], vB[4];
            #pragma unroll
            for (int j = 0; j < 4; j++) { vA[j] = pA[j * 32 + lid];
                                          vB[j] = pB[j * 32 + lid]; }
            float sA = warp_sum((vec_expsum(vA[0]) + vec_expsum(vA[1])) +
                                (vec_expsum(vA[2]) + vec_expsum(vA[3])));
            float sB = warp_sum((vec_expsum(vB[0]) + vec_expsum(vB[1])) +
                                (vec_expsum(vB[2]) + vec_expsum(vB[3])));
            if (lid == 0) {
                acc += (__logf(sA) - sf[(2 * wid + 0) * 512 + tA]) +
                       (__logf(sB) - sf[(2 * wid + 1) * 512 + tB]);
            }
            __syncthreads();
        } else {
            // L0: 32 rows of 128; warp w owns 8 rows; 8 lanes/row, 2 passes.
            const int rb = (c - C1_END) * 32;
            const int g  = lid >> 3;
            const int sl = lid & 7;
            #pragma unroll
            for (int pss = 0; pss < 2; pss++) {
                const int rloc = wid * 8 + pss * 4 + g;
                int tIdx = 0;
                if (sl == 0) tIdx = targets[(rb + rloc) * 4 + 0];
                const float4* gp = st + rloc * 32;
                float a0 = vec_expsum(gp[0 * 8 + sl]) + vec_expsum(gp[1 * 8 + sl]);
                float a1 = vec_expsum(gp[2 * 8 + sl]) + vec_expsum(gp[3 * 8 + sl]);
                float sv = a0 + a1;
                #pragma unroll
                for (int off = 4; off; off >>= 1)
                    sv += __shfl_xor_sync(0xffffffffu, sv, off);
                if (sl == 0) acc += __logf(sv) - sf[rloc * 128 + tIdx];
            }
            __syncthreads();
        }

        // refill stage s (t0's own stage reads above are complete)
        if (tid == 0) {
            const int kn = k + NSTAGE;
            if (kn < ktot) {
                asm volatile("fence.proxy.async.shared::cta;" ::: "memory");
                bulk_load(stg[s], src_of(seq(kn)), CHUNK_BYTES, mb[s]);
            }
        }
    }

    // ---- per-CTA combine ----
    float ws = warp_sum(acc);
    __syncthreads();
    if (lid == 0) swr[wid] = ws;
    __syncthreads();
    if (tid == 0) g_part[bid] = (swr[0] + swr[1]) + (swr[2] + swr[3]);

    // ---- last-block finalize ----
    if (tid == 0) {
        __threadfence();
        int ticket = atomicAdd(&g_done, 1);
        is_last = (ticket == NB_CE - 1);
        if (is_last) g_done = 0;
    }
    __syncthreads();

    if (is_last) {
        float ce = 0.0f;
        for (int i = tid; i < NB_CE; i += 128) ce += __ldcg(&g_part[i]);
        ce = warp_sum(ce);
        __syncthreads();
        if (lid == 0) swr[wid] = ce;
        __syncthreads();
        if (tid == 0) {
            float ce_sum = (swr[0] + swr[1]) + (swr[2] + swr[3]);
            float depcnt = 0.0f;
            #pragma unroll
            for (int j = 0; j < NBD; j++) depcnt += __ldcg(&g_dep[j]);

            const float E_MINUS_1 = 1.7182818284590452f;
            const float inv_b = 1.0f / (float)BATCH;
            float ce_total  = ce_sum * inv_b;
            float dep_total = E_MINUS_1 * depcnt * inv_b;
            out[0] = 0.5f * ce_total + 0.5f * dep_total;
            out[1] = ce_total;
            out[2] = dep_total;
        }
    }
}

extern "C" void kernel_launch(void* const* d_in, const int* in_sizes, int n_in,
                              void* d_out, int out_size) {
    const float* o0 = (const float*)d_in[0];
    const float* o1 = (const float*)d_in[1];
    const float* o2 = (const float*)d_in[2];
    const float* o3 = (const float*)d_in[3];
    const int* targets = (const int*)d_in[4];
    const int* p0 = (const int*)d_in[5];
    const int* p1 = (const int*)d_in[6];
    const int* p2 = (const int*)d_in[7];
    const int* p3 = (const int*)d_in[8];
    const int* v01 = (const int*)d_in[9];
    const int* v12 = (const int*)d_in[10];
    const int* v23 = (const int*)d_in[11];
    float* out = (float*)d_out;

    const size_t smem = NSTAGE * CHUNK_BYTES;   // 49152 B
    cudaFuncSetAttribute(fused_kernel,
                         cudaFuncAttributeMaxDynamicSharedMemorySize, (int)smem);
    fused_kernel<<<NB_CE, 128, smem>>>(o0, o1, o2, o3, targets,
                                       p0, p1, p2, p3, v01, v12, v23, out);
}

// round 13
// speedup vs baseline: 1.0636x; 1.0636x over previous
#include <cuda_runtime.h>
#include <cstdint>

#define BATCH 4096

// ---- uniform 32KB chunks (8192 floats) over concatenated logits ----
#define CHUNK_FLOATS 8192
#define CHUNK_BYTES  32768
#define C3_END 4096              // L3: 1 row/chunk
#define C2_END 5120              // L2: 4 rows/chunk
#define C1_END 5376              // L1: 16 rows/chunk
#define NCHUNK 5440              // L0: 64 rows/chunk

#define NB_CE 296                // 2 CTAs/SM x 148 SMs; one exact wave
#define NBD 8                    // dep folded into CTAs 0..7
#define NSTAGE 3
#define MAXK 19                  // ceil(5440/296)

__device__ float g_part[NB_CE];
__device__ float g_dep[NBD];
__device__ int   g_done;         // zero-init; self-resets each replay

__device__ __forceinline__ float vec_expsum(float4 v) {
    return __expf(v.x) + __expf(v.y) + __expf(v.z) + __expf(v.w);
}
__device__ __forceinline__ float warp_sum(float s) {
    #pragma unroll
    for (int off = 16; off; off >>= 1)
        s += __shfl_xor_sync(0xffffffffu, s, off);
    return s;
}
__device__ __forceinline__ uint32_t smem_u32(const void* p) {
    return (uint32_t)__cvta_generic_to_shared(p);
}
__device__ __forceinline__ void mbar_init(uint32_t a) {
    asm volatile("mbarrier.init.shared.b64 [%0], 1;" :: "r"(a) : "memory");
}
__device__ __forceinline__ void mbar_wait(uint32_t a, int parity) {
    asm volatile(
        "{\n\t.reg .pred P;\n\t"
        "W%=:\n\t"
        "mbarrier.try_wait.parity.acquire.cta.shared::cta.b64 P, [%0], %1, 0x989680;\n\t"
        "@P bra D%=;\n\t"
        "bra W%=;\n\t"
        "D%=:\n\t}"
        :: "r"(a), "r"(parity) : "memory");
}
__device__ __forceinline__ void bulk_load(uint32_t dst, const void* src,
                                          uint32_t bytes, uint32_t mbar) {
    asm volatile("mbarrier.arrive.expect_tx.shared.b64 _, [%0], %1;"
                 :: "r"(mbar), "r"(bytes) : "memory");
    asm volatile(
        "cp.async.bulk.shared::cluster.global.mbarrier::complete_tx::bytes "
        "[%0], [%1], %2, [%3];"
        :: "r"(dst), "l"(src), "r"(bytes), "r"(mbar) : "memory");
}

__global__ void __launch_bounds__(256)
fused_kernel(const float* __restrict__ o0, const float* __restrict__ o1,
             const float* __restrict__ o2, const float* __restrict__ o3,
             const int* __restrict__ targets,
             const int* __restrict__ p0, const int* __restrict__ p1,
             const int* __restrict__ p2, const int* __restrict__ p3,
             const int* __restrict__ v01, const int* __restrict__ v12,
             const int* __restrict__ v23,
             float* __restrict__ out) {
    extern __shared__ float stage[];              // NSTAGE * 8192 floats
    __shared__ unsigned long long mbar_s[NSTAGE];
    __shared__ float sws[2][8];                   // double-buffered warp partials
    __shared__ float swr[8];
    __shared__ int   tpref[MAXK * 4];             // prefetched L3/L2 target indices
    __shared__ bool  is_last;

    const int bid = blockIdx.x;
    const int tid = threadIdx.x;
    const int wid = tid >> 5;
    const int lid = tid & 31;

    float acc = 0.0f;

    uint32_t mb[NSTAGE], stg[NSTAGE];
    #pragma unroll
    for (int s = 0; s < NSTAGE; s++) {
        mb[s]  = smem_u32(&mbar_s[s]);
        stg[s] = smem_u32(&stage[s * CHUNK_FLOATS]);
    }
    if (tid == 0) {
        #pragma unroll
        for (int s = 0; s < NSTAGE; s++) mbar_init(mb[s]);
    }
    __syncthreads();

    auto src_of = [&](int c) -> const float* {
        if (c < C3_END) return o3 + (size_t)c * CHUNK_FLOATS;
        if (c < C2_END) return o2 + (size_t)(c - C3_END) * CHUNK_FLOATS;
        if (c < C1_END) return o1 + (size_t)(c - C2_END) * CHUNK_FLOATS;
        return o0 + (size_t)(c - C1_END) * CHUNK_FLOATS;
    };

    if (tid == 0) {
        #pragma unroll
        for (int kp = 0; kp < NSTAGE; kp++) {
            int c = bid + kp * NB_CE;
            if (c < NCHUNK) bulk_load(stg[kp], src_of(c), CHUNK_BYTES, mb[kp]);
        }
        // Prefetch this CTA's L3/L2 target indices (independent LDGs, pipelined;
        // hidden under pipeline fill). Removes ~250-600cyc LDG from every t0 tail.
        int kk = 0;
        for (int c = bid; c < C2_END; c += NB_CE, kk++) {
            if (c < C3_END) {
                tpref[kk * 4] = targets[c * 4 + 3];
            } else {
                const int rb = (c - C3_END) * 4;
                tpref[kk * 4 + 0] = targets[(rb + 0) * 4 + 2];
                tpref[kk * 4 + 1] = targets[(rb + 1) * 4 + 2];
                tpref[kk * 4 + 2] = targets[(rb + 2) * 4 + 2];
                tpref[kk * 4 + 3] = targets[(rb + 3) * 4 + 2];
            }
        }
    }

    // ---- dep work folded into CTAs 0..7, hidden under pipeline fill ----
    if (bid < NBD) {
        const int base = bid * 512;
        float cnt = 0.0f;
        #pragma unroll
        for (int rep = 0; rep < 2; rep++) {
            const int i = base + rep * 256 + tid;
            const int a = p0[i], b = p1[i], cc = p2[i], e = p3[i];
            cnt += (v01[a * 512   + b ] == 0) ? 1.0f : 0.0f;
            cnt += (v12[b * 2048  + cc] == 0) ? 1.0f : 0.0f;
            cnt += (v23[cc * 8192 + e ] == 0) ? 1.0f : 0.0f;
        }
        cnt = warp_sum(cnt);
        if (lid == 0) swr[wid] = cnt;
        __syncthreads();
        if (tid == 0) {
            float a = 0.0f;
            #pragma unroll
            for (int w = 0; w < 8; w++) a += swr[w];
            g_dep[bid] = a;
        }
        __syncthreads();
    }

    // ---- main pipelined loop (R8 structure) ----
    for (int k = 0, c = bid; c < NCHUNK; k++, c += NB_CE) {
        const int s = k % NSTAGE;
        const int parity = (k / NSTAGE) & 1;
        const int pb = k & 1;
        mbar_wait(mb[s], parity);

        const float*  sf = stage + s * CHUNK_FLOATS;
        const float4* st = (const float4*)sf;

        if (c < C2_END) {
            // L3/L2: per-warp partial over its 1024-float segment.
            const float4* wp = st + wid * 256;
            float a0 = 0.f, a1 = 0.f, a2 = 0.f, a3 = 0.f;
            #pragma unroll
            for (int kk = 0; kk < 2; kk++) {
                a0 += vec_expsum(wp[(kk * 4 + 0) * 32 + lid]);
                a1 += vec_expsum(wp[(kk * 4 + 1) * 32 + lid]);
                a2 += vec_expsum(wp[(kk * 4 + 2) * 32 + lid]);
                a3 += vec_expsum(wp[(kk * 4 + 3) * 32 + lid]);
            }
            float sw = warp_sum((a0 + a1) + (a2 + a3));
            if (lid == 0) sws[pb][wid] = sw;
        } else if (c < C1_END) {
            // L1: 16 rows of 512; half-warp per row.
            const int h  = lid >> 4;
            const int sl = lid & 15;
            const int rl = wid * 2 + h;
            int tIdx = 0;
            if (sl == 0) tIdx = targets[((c - C2_END) * 16 + rl) * 4 + 1];
            const float4* wp = st + wid * 256 + h * 128;
            float a0 = 0.f, a1 = 0.f;
            #pragma unroll
            for (int kk = 0; kk < 8; kk += 2) {
                a0 += vec_expsum(wp[(kk + 0) * 16 + sl]);
                a1 += vec_expsum(wp[(kk + 1) * 16 + sl]);
            }
            float sv = a0 + a1;
            #pragma unroll
            for (int off = 8; off; off >>= 1)
                sv += __shfl_xor_sync(0xffffffffu, sv, off);
            if (sl == 0) acc += __logf(sv) - sf[rl * 512 + tIdx];
        } else {
            // L0: 64 rows of 128; lane-quad per row.
            const int g = lid >> 2;
            const int q = lid & 3;
            const int rl = wid * 8 + g;
            int tIdx = 0;
            if (q == 0) tIdx = targets[((c - C1_END) * 64 + rl) * 4 + 0];
            const float4* gp = st + wid * 256 + g * 32;
            float a0 = 0.f, a1 = 0.f;
            #pragma unroll
            for (int kk = 0; kk < 8; kk += 2) {
                a0 += vec_expsum(gp[(kk + 0) * 4 + q]);
                a1 += vec_expsum(gp[(kk + 1) * 4 + q]);
            }
            float sv = a0 + a1;
            #pragma unroll
            for (int off = 2; off; off >>= 1)
                sv += __shfl_xor_sync(0xffffffffu, sv, off);
            if (q == 0) acc += __logf(sv) - sf[rl * 128 + tIdx];
        }

        __syncthreads();   // all reads of stage s complete; sws[pb] published

        if (tid == 0) {
            if (c < C3_END) {
                float ssum = ((sws[pb][0] + sws[pb][1]) + (sws[pb][2] + sws[pb][3])) +
                             ((sws[pb][4] + sws[pb][5]) + (sws[pb][6] + sws[pb][7]));
                acc += __logf(ssum) - sf[tpref[k * 4]];      // smem idx, no LDG
            } else if (c < C2_END) {
                #pragma unroll
                for (int j = 0; j < 4; j++) {
                    float rs = sws[pb][2 * j] + sws[pb][2 * j + 1];
                    acc += __logf(rs) - sf[j * 2048 + tpref[k * 4 + j]];
                }
            }
            const int cn = c + NSTAGE * NB_CE;
            if (cn < NCHUNK) {
                asm volatile("fence.proxy.async.shared::cta;" ::: "memory");
                bulk_load(stg[s], src_of(cn), CHUNK_BYTES, mb[s]);
            }
        }
    }

    // ---- per-CTA combine ----
    float ws = warp_sum(acc);
    __syncthreads();
    if (lid == 0) swr[wid] = ws;
    __syncthreads();
    if (tid == 0) {
        float a = 0.0f;
        #pragma unroll
        for (int w = 0; w < 8; w++) a += swr[w];
        g_part[bid] = a;
    }

    // ---- last-block finalize ----
    if (tid == 0) {
        __threadfence();
        int ticket = atomicAdd(&g_done, 1);
        is_last = (ticket == NB_CE - 1);
        if (is_last) g_done = 0;
    }
    __syncthreads();

    if (is_last) {
        float ce = 0.0f;
        for (int i = tid; i < NB_CE; i += 256) ce += __ldcg(&g_part[i]);
        ce = warp_sum(ce);
        __syncthreads();
        if (lid == 0) swr[wid] = ce;
        __syncthreads();
        if (tid == 0) {
            float ce_sum = 0.0f;
            #pragma unroll
            for (int w = 0; w < 8; w++) ce_sum += swr[w];
            float depcnt = 0.0f;
            #pragma unroll
            for (int j = 0; j < NBD; j++) depcnt += __ldcg(&g_dep[j]);

            const float E_MINUS_1 = 1.7182818284590452f;
            const float inv_b = 1.0f / (float)BATCH;
            float ce_total  = ce_sum * inv_b;
            float dep_total = E_MINUS_1 * depcnt * inv_b;
            out[0] = 0.5f * ce_total + 0.5f * dep_total;
            out[1] = ce_total;
            out[2] = dep_total;
        }
    }
}

extern "C" void kernel_launch(void* const* d_in, const int* in_sizes, int n_in,
                              void* d_out, int out_size) {
    const float* o0 = (const float*)d_in[0];
    const float* o1 = (const float*)d_in[1];
    const float* o2 = (const float*)d_in[2];
    const float* o3 = (const float*)d_in[3];
    const int* targets = (const int*)d_in[4];
    const int* p0 = (const int*)d_in[5];
    const int* p1 = (const int*)d_in[6];
    const int* p2 = (const int*)d_in[7];
    const int* p3 = (const int*)d_in[8];
    const int* v01 = (const int*)d_in[9];
    const int* v12 = (const int*)d_in[10];
    const int* v23 = (const int*)d_in[11];
    float* out = (float*)d_out;

    const size_t smem = NSTAGE * CHUNK_BYTES;   // 98304 B
    cudaFuncSetAttribute(fused_kernel,
                         cudaFuncAttributeMaxDynamicSharedMemorySize, (int)smem);
    fused_kernel<<<NB_CE, 256, smem>>>(o0, o1, o2, o3, targets,
                                       p0, p1, p2, p3, v01, v12, v23, out);
}

// round 14
// speedup vs baseline: 1.3179x; 1.2391x over previous
#include <cuda_runtime.h>
#include <cstdint>

#define BATCH 4096

// ---- uniform 32KB chunks (8192 floats) over concatenated logits ----
#define CHUNK_FLOATS 8192
#define CHUNK_BYTES  32768
#define C3_END 4096              // L3: 1 row/chunk
#define C2_END 5120              // L2: 4 rows/chunk
#define C1_END 5376              // L1: 16 rows/chunk
#define NCHUNK 5440              // L0: 64 rows/chunk

#define NB_CE 296                // 2 CTAs/SM x 148 SMs; one exact wave
#define NSTAGE 3
#define MAXK 19                  // ceil(5440/296)
#define DEP_PER_CTA 14           // ceil(4096/296)

__device__ float g_part[NB_CE];
__device__ float g_depA[NB_CE];
__device__ int   g_done;         // zero-init; self-resets each replay

__device__ __forceinline__ float vec_expsum(float4 v) {
    return __expf(v.x) + __expf(v.y) + __expf(v.z) + __expf(v.w);
}
__device__ __forceinline__ float warp_sum(float s) {
    #pragma unroll
    for (int off = 16; off; off >>= 1)
        s += __shfl_xor_sync(0xffffffffu, s, off);
    return s;
}
__device__ __forceinline__ uint32_t smem_u32(const void* p) {
    return (uint32_t)__cvta_generic_to_shared(p);
}
__device__ __forceinline__ void mbar_init(uint32_t a) {
    asm volatile("mbarrier.init.shared.b64 [%0], 1;" :: "r"(a) : "memory");
}
__device__ __forceinline__ void mbar_wait(uint32_t a, int parity) {
    asm volatile(
        "{\n\t.reg .pred P;\n\t"
        "W%=:\n\t"
        "mbarrier.try_wait.parity.acquire.cta.shared::cta.b64 P, [%0], %1, 0x989680;\n\t"
        "@P bra D%=;\n\t"
        "bra W%=;\n\t"
        "D%=:\n\t}"
        :: "r"(a), "r"(parity) : "memory");
}
__device__ __forceinline__ void bulk_load(uint32_t dst, const void* src,
                                          uint32_t bytes, uint32_t mbar) {
    asm volatile("mbarrier.arrive.expect_tx.shared.b64 _, [%0], %1;"
                 :: "r"(mbar), "r"(bytes) : "memory");
    asm volatile(
        "cp.async.bulk.shared::cluster.global.mbarrier::complete_tx::bytes "
        "[%0], [%1], %2, [%3];"
        :: "r"(dst), "l"(src), "r"(bytes), "r"(mbar) : "memory");
}

__global__ void __launch_bounds__(256)
fused_kernel(const float* __restrict__ o0, const float* __restrict__ o1,
             const float* __restrict__ o2, const float* __restrict__ o3,
             const int* __restrict__ targets,
             const int* __restrict__ p0, const int* __restrict__ p1,
             const int* __restrict__ p2, const int* __restrict__ p3,
             const int* __restrict__ v01, const int* __restrict__ v12,
             const int* __restrict__ v23,
             float* __restrict__ out) {
    extern __shared__ float stage[];              // NSTAGE * 8192 floats
    __shared__ unsigned long long mbar_s[NSTAGE];
    __shared__ float sws[2][8];                   // double-buffered warp partials
    __shared__ float swr[8];
    __shared__ int   tpref[MAXK * 4];             // prefetched L3/L2 target indices
    __shared__ bool  is_last;

    const int bid = blockIdx.x;
    const int tid = threadIdx.x;
    const int wid = tid >> 5;
    const int lid = tid & 31;

    float acc = 0.0f;

    uint32_t mb[NSTAGE], stg[NSTAGE];
    #pragma unroll
    for (int s = 0; s < NSTAGE; s++) {
        mb[s]  = smem_u32(&mbar_s[s]);
        stg[s] = smem_u32(&stage[s * CHUNK_FLOATS]);
    }
    if (tid == 0) {
        #pragma unroll
        for (int s = 0; s < NSTAGE; s++) mbar_init(mb[s]);
    }
    __syncthreads();

    auto src_of = [&](int c) -> const float* {
        if (c < C3_END) return o3 + (size_t)c * CHUNK_FLOATS;
        if (c < C2_END) return o2 + (size_t)(c - C3_END) * CHUNK_FLOATS;
        if (c < C1_END) return o1 + (size_t)(c - C2_END) * CHUNK_FLOATS;
        return o0 + (size_t)(c - C1_END) * CHUNK_FLOATS;
    };

    if (tid == 0) {
        #pragma unroll
        for (int kp = 0; kp < NSTAGE; kp++) {
            int c = bid + kp * NB_CE;
            if (c < NCHUNK) bulk_load(stg[kp], src_of(c), CHUNK_BYTES, mb[kp]);
        }
    }

    // ---- parallel target prefetch: thread k handles its own chunk k ----
    if (tid < MAXK) {
        const int c = bid + tid * NB_CE;
        if (c < C3_END) {
            tpref[tid * 4] = targets[c * 4 + 3];
        } else if (c < C2_END) {
            const int rb = (c - C3_END) * 4;
            tpref[tid * 4 + 0] = targets[(rb + 0) * 4 + 2];
            tpref[tid * 4 + 1] = targets[(rb + 1) * 4 + 2];
            tpref[tid * 4 + 2] = targets[(rb + 2) * 4 + 2];
            tpref[tid * 4 + 3] = targets[(rb + 3) * 4 + 2];
        }
    }

    // ---- dep spread over ALL CTAs: one sample/thread, warp 0 only ----
    {
        float cnt = 0.0f;
        if (tid < DEP_PER_CTA) {
            const int i = bid * DEP_PER_CTA + tid;
            if (i < BATCH) {
                const int a = p0[i], b = p1[i], cc = p2[i], e = p3[i];
                cnt += (v01[a * 512   + b ] == 0) ? 1.0f : 0.0f;
                cnt += (v12[b * 2048  + cc] == 0) ? 1.0f : 0.0f;
                cnt += (v23[cc * 8192 + e ] == 0) ? 1.0f : 0.0f;
            }
        }
        if (wid == 0) {
            cnt = warp_sum(cnt);
            if (lid == 0) g_depA[bid] = cnt;
        }
    }

    // ---- main pipelined loop (R8 structure, t0 owns refills) ----
    for (int k = 0, c = bid; c < NCHUNK; k++, c += NB_CE) {
        const int s = k % NSTAGE;
        const int parity = (k / NSTAGE) & 1;
        const int pb = k & 1;
        mbar_wait(mb[s], parity);

        const float*  sf = stage + s * CHUNK_FLOATS;
        const float4* st = (const float4*)sf;

        if (c < C2_END) {
            // L3/L2: per-warp partial over its 1024-float segment.
            const float4* wp = st + wid * 256;
            float a0 = 0.f, a1 = 0.f, a2 = 0.f, a3 = 0.f;
            #pragma unroll
            for (int kk = 0; kk < 2; kk++) {
                a0 += vec_expsum(wp[(kk * 4 + 0) * 32 + lid]);
                a1 += vec_expsum(wp[(kk * 4 + 1) * 32 + lid]);
                a2 += vec_expsum(wp[(kk * 4 + 2) * 32 + lid]);
                a3 += vec_expsum(wp[(kk * 4 + 3) * 32 + lid]);
            }
            float sw = warp_sum((a0 + a1) + (a2 + a3));
            if (lid == 0) sws[pb][wid] = sw;
        } else if (c < C1_END) {
            // L1: 16 rows of 512; half-warp per row.
            const int h  = lid >> 4;
            const int sl = lid & 15;
            const int rl = wid * 2 + h;
            int tIdx = 0;
            if (sl == 0) tIdx = targets[((c - C2_END) * 16 + rl) * 4 + 1];
            const float4* wp = st + wid * 256 + h * 128;
            float a0 = 0.f, a1 = 0.f;
            #pragma unroll
            for (int kk = 0; kk < 8; kk += 2) {
                a0 += vec_expsum(wp[(kk + 0) * 16 + sl]);
                a1 += vec_expsum(wp[(kk + 1) * 16 + sl]);
            }
            float sv = a0 + a1;
            #pragma unroll
            for (int off = 8; off; off >>= 1)
                sv += __shfl_xor_sync(0xffffffffu, sv, off);
            if (sl == 0) acc += __logf(sv) - sf[rl * 512 + tIdx];
        } else {
            // L0: 64 rows of 128; lane-quad per row.
            const int g = lid >> 2;
            const int q = lid & 3;
            const int rl = wid * 8 + g;
            int tIdx = 0;
            if (q == 0) tIdx = targets[((c - C1_END) * 64 + rl) * 4 + 0];
            const float4* gp = st + wid * 256 + g * 32;
            float a0 = 0.f, a1 = 0.f;
            #pragma unroll
            for (int kk = 0; kk < 8; kk += 2) {
                a0 += vec_expsum(gp[(kk + 0) * 4 + q]);
                a1 += vec_expsum(gp[(kk + 1) * 4 + q]);
            }
            float sv = a0 + a1;
            #pragma unroll
            for (int off = 2; off; off >>= 1)
                sv += __shfl_xor_sync(0xffffffffu, sv, off);
            if (q == 0) acc += __logf(sv) - sf[rl * 128 + tIdx];
        }

        __syncthreads();   // all reads of stage s complete; sws[pb] published

        if (tid == 0) {
            if (c < C3_END) {
                float ssum = ((sws[pb][0] + sws[pb][1]) + (sws[pb][2] + sws[pb][3])) +
                             ((sws[pb][4] + sws[pb][5]) + (sws[pb][6] + sws[pb][7]));
                acc += __logf(ssum) - sf[tpref[k * 4]];      // smem idx, no LDG
            } else if (c < C2_END) {
                #pragma unroll
                for (int j = 0; j < 4; j++) {
                    float rs = sws[pb][2 * j] + sws[pb][2 * j + 1];
                    acc += __logf(rs) - sf[j * 2048 + tpref[k * 4 + j]];
                }
            }
            const int cn = c + NSTAGE * NB_CE;
            if (cn < NCHUNK) {
                asm volatile("fence.proxy.async.shared::cta;" ::: "memory");
                bulk_load(stg[s], src_of(cn), CHUNK_BYTES, mb[s]);
            }
        }
    }

    // ---- per-CTA combine ----
    float ws = warp_sum(acc);
    __syncthreads();
    if (lid == 0) swr[wid] = ws;
    __syncthreads();
    if (tid == 0) {
        float a = 0.0f;
        #pragma unroll
        for (int w = 0; w < 8; w++) a += swr[w];
        g_part[bid] = a;
    }

    // ---- last-block finalize ----
    if (tid == 0) {
        __threadfence();
        int ticket = atomicAdd(&g_done, 1);
        is_last = (ticket == NB_CE - 1);
        if (is_last) g_done = 0;
    }
    __syncthreads();

    if (is_last) {
        float ce = 0.0f, dep = 0.0f;
        for (int i = tid; i < NB_CE; i += 256) {
            ce  += __ldcg(&g_part[i]);
            dep += __ldcg(&g_depA[i]);
        }
        ce  = warp_sum(ce);
        dep = warp_sum(dep);
        __syncthreads();
        if (lid == 0) { swr[wid] = ce; sws[0][wid] = dep; }
        __syncthreads();
        if (tid == 0) {
            float ce_sum = 0.0f, depcnt = 0.0f;
            #pragma unroll
            for (int w = 0; w < 8; w++) { ce_sum += swr[w]; depcnt += sws[0][w]; }

            const float E_MINUS_1 = 1.7182818284590452f;
            const float inv_b = 1.0f / (float)BATCH;
            float ce_total  = ce_sum * inv_b;
            float dep_total = E_MINUS_1 * depcnt * inv_b;
            out[0] = 0.5f * ce_total + 0.5f * dep_total;
            out[1] = ce_total;
            out[2] = dep_total;
        }
    }
}

extern "C" void kernel_launch(void* const* d_in, const int* in_sizes, int n_in,
                              void* d_out, int out_size) {
    const float* o0 = (const float*)d_in[0];
    const float* o1 = (const float*)d_in[1];
    const float* o2 = (const float*)d_in[2];
    const float* o3 = (const float*)d_in[3];
    const int* targets = (const int*)d_in[4];
    const int* p0 = (const int*)d_in[5];
    const int* p1 = (const int*)d_in[6];
    const int* p2 = (const int*)d_in[7];
    const int* p3 = (const int*)d_in[8];
    const int* v01 = (const int*)d_in[9];
    const int* v12 = (const int*)d_in[10];
    const int* v23 = (const int*)d_in[11];
    float* out = (float*)d_out;

    const size_t smem = NSTAGE * CHUNK_BYTES;   // 98304 B
    cudaFuncSetAttribute(fused_kernel,
                         cudaFuncAttributeMaxDynamicSharedMemorySize, (int)smem);
    fused_kernel<<<NB_CE, 256, smem>>>(o0, o1, o2, o3, targets,
                                       p0, p1, p2, p3, v01, v12, v23, out);
}